// round 1
// baseline (speedup 1.0000x reference)
#include <cuda_runtime.h>
#include <cstdint>

#define NUM_E  16384
#define DIM    256
#define NVEC   8192     // B*H*W
#define Bc     8
#define Cc     256
#define Hc     32
#define Wc     32

#define BM 128
#define BN 128
#define BK 16
#define PAD 4           // shared padding (keeps 16B alignment, reduces bank conflicts)

// Scratch (no allocations allowed): 8 MB + 16 MB + 64 KB
__device__ float g_zt[(size_t)NVEC * DIM];           // z transposed to [N, D] (unnormalized: argmax is scale-invariant)
__device__ float g_en[(size_t)NUM_E * DIM];          // normalized codebook
__device__ unsigned long long g_best[NVEC];          // packed (enc(score) << 32) | (~col)

// monotonic float -> uint encoding (order-preserving for all finite floats)
__device__ __forceinline__ unsigned enc_f(float f) {
    unsigned u = __float_as_uint(f);
    return (u & 0x80000000u) ? ~u : (u | 0x80000000u);
}

// ---------------------------------------------------------------- init ----
__global__ void k_init() {
    g_best[blockIdx.x * 256 + threadIdx.x] = 0ULL;
}

// ------------------------------------------------- normalize codebook ----
// 8 warps/block, one row per warp. Row = 256 consecutive floats, coalesced.
__global__ void k_norm_emb(const float* __restrict__ w) {
    int row  = blockIdx.x * 8 + (threadIdx.x >> 5);
    int lane = threadIdx.x & 31;
    const float* src = w + (size_t)row * DIM;
    float vals[8];
    float s = 0.f;
#pragma unroll
    for (int j = 0; j < 8; j++) {
        float x = src[lane + 32 * j];
        vals[j] = x;
        s += x * x;
    }
#pragma unroll
    for (int o = 16; o; o >>= 1) s += __shfl_xor_sync(0xFFFFFFFFu, s, o);
    float n = __fsqrt_rn(s);
    float m = fmaxf(n, 1e-12f);
    float* dst = g_en + (size_t)row * DIM;
#pragma unroll
    for (int j = 0; j < 8; j++) dst[lane + 32 * j] = __fdiv_rn(vals[j], m);
}

// ------------------------------------------------------- transpose z ----
// One block per (b,h). Read z[b][c][h][w] coalesced over w, write [n][c]
// coalesced over c via padded shared tile. No normalization needed:
// argmax over codes is invariant to positive per-row scaling of z.
__global__ void k_trans_z(const float* __restrict__ z) {
    __shared__ float s[DIM][33];
    int bh = blockIdx.x;
    int b = bh >> 5, h = bh & 31;
    int tx = threadIdx.x & 31;   // w
    int ty = threadIdx.x >> 5;   // 0..7
    const float* base = z + (size_t)b * Cc * Hc * Wc + (size_t)h * Wc;
#pragma unroll
    for (int j = 0; j < 32; j++) {
        int c = ty + 8 * j;
        s[c][tx] = base[(size_t)c * Hc * Wc + tx];
    }
    __syncthreads();
#pragma unroll
    for (int m = 0; m < 4; m++) {
        int wv = ty + 8 * m;                 // vector (w) handled by this warp
        int n  = bh * 32 + wv;
        float* dst = g_zt + (size_t)n * DIM;
#pragma unroll
        for (int j = 0; j < 8; j++) {
            int c = tx + 32 * j;
            dst[c] = s[c][wv];
        }
    }
}

// ------------------------------------------------- fused GEMM + argmax ----
// score[n][k] = z[n] . e[k]; track per-row max (value, smallest col on tie).
__global__ __launch_bounds__(256, 2) void k_gemm_argmax() {
    __shared__ float sA[BK][BM + PAD];
    __shared__ float sB[BK][BN + PAD];
    __shared__ unsigned long long sBest[BM];

    int tid = threadIdx.x;
    int tx = tid & 15;          // 0..15 -> col group
    int ty = tid >> 4;          // 0..15 -> row group
    int rowBase = blockIdx.y * BM;
    int colBase = blockIdx.x * BN;

    const float* Ag = g_zt + (size_t)rowBase * DIM;
    const float* Bg = g_en + (size_t)colBase * DIM;

    float acc[8][8];
#pragma unroll
    for (int i = 0; i < 8; i++)
#pragma unroll
        for (int j = 0; j < 8; j++) acc[i][j] = 0.f;

    if (tid < BM) sBest[tid] = 0ULL;

    for (int k0 = 0; k0 < DIM; k0 += BK) {
#pragma unroll
        for (int i = 0; i < 2; i++) {
            int l = tid + i * 256;          // 0..511
            int r = l >> 2;                 // 0..127
            int kq = (l & 3) * 4;           // 0,4,8,12
            float4 a = *(const float4*)(Ag + (size_t)r * DIM + k0 + kq);
            sA[kq + 0][r] = a.x; sA[kq + 1][r] = a.y;
            sA[kq + 2][r] = a.z; sA[kq + 3][r] = a.w;
            float4 bv = *(const float4*)(Bg + (size_t)r * DIM + k0 + kq);
            sB[kq + 0][r] = bv.x; sB[kq + 1][r] = bv.y;
            sB[kq + 2][r] = bv.z; sB[kq + 3][r] = bv.w;
        }
        __syncthreads();
#pragma unroll
        for (int k = 0; k < BK; k++) {
            float4 a0 = *(const float4*)&sA[k][ty * 8];
            float4 a1 = *(const float4*)&sA[k][ty * 8 + 4];
            float4 b0 = *(const float4*)&sB[k][tx * 8];
            float4 b1 = *(const float4*)&sB[k][tx * 8 + 4];
            float av[8] = {a0.x, a0.y, a0.z, a0.w, a1.x, a1.y, a1.z, a1.w};
            float bv[8] = {b0.x, b0.y, b0.z, b0.w, b1.x, b1.y, b1.z, b1.w};
#pragma unroll
            for (int i = 0; i < 8; i++)
#pragma unroll
                for (int j = 0; j < 8; j++)
                    acc[i][j] = fmaf(av[i], bv[j], acc[i][j]);
        }
        __syncthreads();
    }

    // per-thread argmax over its 8 cols for each of its 8 rows
#pragma unroll
    for (int i = 0; i < 8; i++) {
        float best = acc[i][0];
        int bj = 0;
#pragma unroll
        for (int j = 1; j < 8; j++)
            if (acc[i][j] > best) { best = acc[i][j]; bj = j; }
        unsigned col = (unsigned)(colBase + tx * 8 + bj);
        unsigned long long key =
            ((unsigned long long)enc_f(best) << 32) | (unsigned long long)(0xFFFFFFFFu - col);
        atomicMax(&sBest[ty * 8 + i], key);
    }
    __syncthreads();
    if (tid < BM) atomicMax(&g_best[rowBase + tid], sBest[tid]);
}

// -------------------------------------------------------- output pass ----
// z_q[b][c][h][w] = e_norm[idx(n)][c]; indices (as float) appended after z_q.
__global__ void k_out(float* __restrict__ out) {
    __shared__ unsigned kidx[32];
    int bh = blockIdx.x;
    int b = bh >> 5, h = bh & 31;
    int tx = threadIdx.x & 31;   // w
    int ty = threadIdx.x >> 5;   // 0..7
    int n = bh * 32 + tx;
    if (ty == 0) {
        unsigned long long key = g_best[n];
        unsigned k = 0xFFFFFFFFu - (unsigned)(key & 0xFFFFFFFFu);
        kidx[tx] = k;
        out[(size_t)NVEC * DIM + n] = (float)k;
    }
    __syncthreads();
    unsigned k = kidx[tx];
    const float* src = g_en + (size_t)k * DIM;
    float* zq = out + (size_t)b * Cc * Hc * Wc + (size_t)h * Wc;
#pragma unroll
    for (int j = 0; j < 32; j++) {
        int c = ty + 8 * j;
        zq[(size_t)c * Hc * Wc + tx] = src[c];
    }
}

extern "C" void kernel_launch(void* const* d_in, const int* in_sizes, int n_in,
                              void* d_out, int out_size) {
    (void)n_in; (void)out_size;
    const float* z = (const float*)d_in[0];
    const float* w = (const float*)d_in[1];
    // defensive: identify by element count (z: 2,097,152 ; emb: 4,194,304)
    if (in_sizes[0] == NUM_E * DIM) { const float* t = z; z = w; w = t; }

    k_init<<<NVEC / 256, 256>>>();
    k_norm_emb<<<NUM_E / 8, 256>>>(w);
    k_trans_z<<<Bc * Hc, 256>>>(z);
    dim3 grid(NUM_E / BN, NVEC / BM);
    k_gemm_argmax<<<grid, 256>>>();
    k_out<<<Bc * Hc, 256>>>((float*)d_out);
}

// round 3
// speedup vs baseline: 2.4826x; 2.4826x over previous
#include <cuda_runtime.h>
#include <cuda_bf16.h>
#include <cstdint>

#define NUM_E  16384
#define DIM    256
#define NVEC   8192
#define K3     768          // 3*DIM: [hi|hi|lo] . [hi|lo|hi] split-GEMM
#define Bc     8
#define Cc     256
#define Hc     32
#define Wc     32

#define BM 128
#define BN 128
#define BK 32
#define KSTEPS (K3 / BK)          // 24
#define ROWB   80                 // smem row stride bytes (32 bf16 + 16B pad), 16B-mult
#define STAGE_A (BM * ROWB)       // 10240
#define STAGE_BYTES (STAGE_A + BN * ROWB)  // 20480
#define NSTAGE 3
#define SMEM_TOTAL (NSTAGE * STAGE_BYTES)  // 61440

// ---- scratch (__device__ globals; allocations are forbidden) ----
__device__ __align__(256) __nv_bfloat16 g_A[(size_t)NVEC * K3];    // 12 MB
__device__ __align__(256) __nv_bfloat16 g_B[(size_t)NUM_E * K3];   // 24 MB
__device__ __align__(256) float g_en[(size_t)NUM_E * DIM];         // 16 MB exact normalized codebook
__device__ unsigned long long g_best[NVEC];

// ======================= helpers =======================
__device__ __forceinline__ uint32_t smem_u32(const void* p) {
    uint32_t a;
    asm("{ .reg .u64 t; cvta.to.shared.u64 t, %1; cvt.u32.u64 %0, t; }" : "=r"(a) : "l"(p));
    return a;
}
__device__ __forceinline__ void cp16(uint32_t dst, const void* src) {
    asm volatile("cp.async.cg.shared.global [%0], [%1], 16;" :: "r"(dst), "l"(src));
}
#define CP_COMMIT() asm volatile("cp.async.commit_group;" ::: "memory")
#define CP_WAIT2()  asm volatile("cp.async.wait_group 2;" ::: "memory")

__device__ __forceinline__ void ldsm4(uint32_t* r, uint32_t addr) {
    asm volatile("ldmatrix.sync.aligned.m8n8.x4.shared.b16 {%0,%1,%2,%3}, [%4];"
        : "=r"(r[0]), "=r"(r[1]), "=r"(r[2]), "=r"(r[3]) : "r"(addr));
}
__device__ __forceinline__ void mma16816(float* d, const uint32_t* a, uint32_t b0, uint32_t b1) {
    asm volatile("mma.sync.aligned.m16n8k16.row.col.f32.bf16.bf16.f32 "
        "{%0,%1,%2,%3}, {%4,%5,%6,%7}, {%8,%9}, {%0,%1,%2,%3};"
        : "+f"(d[0]), "+f"(d[1]), "+f"(d[2]), "+f"(d[3])
        : "r"(a[0]), "r"(a[1]), "r"(a[2]), "r"(a[3]), "r"(b0), "r"(b1));
}
__device__ __forceinline__ unsigned enc_f(float f) {
    unsigned u = __float_as_uint(f);
    return (u & 0x80000000u) ? ~u : (u | 0x80000000u);
}

// ============================== init ==============================
__global__ void k_init() { g_best[blockIdx.x * 256 + threadIdx.x] = 0ULL; }

// =================== prep A: transpose z + bf16 split ===================
__global__ void k_prep_a(const float* __restrict__ z) {
    __shared__ float s[DIM][33];
    int bh = blockIdx.x;
    int b = bh >> 5, h = bh & 31;
    int tx = threadIdx.x & 31;   // w
    int ty = threadIdx.x >> 5;   // 0..7
    const float* base = z + (size_t)b * Cc * Hc * Wc + (size_t)h * Wc;
#pragma unroll
    for (int j = 0; j < 32; j++) {
        int c = ty + 8 * j;
        s[c][tx] = base[(size_t)c * Hc * Wc + tx];
    }
    __syncthreads();
#pragma unroll
    for (int m = 0; m < 4; m++) {
        int wv = ty + 8 * m;
        int n = bh * 32 + wv;
        __nv_bfloat16* dst = g_A + (size_t)n * K3;
#pragma unroll
        for (int j = 0; j < 8; j++) {
            int c = tx + 32 * j;
            float x = s[c][wv];
            __nv_bfloat16 hi = __float2bfloat16(x);
            __nv_bfloat16 lo = __float2bfloat16(x - __bfloat162float(hi));
            dst[c] = hi; dst[DIM + c] = hi; dst[2 * DIM + c] = lo;
        }
    }
}

// =============== prep B: normalize codebook + bf16 split ===============
__global__ void k_prep_b(const float* __restrict__ w) {
    int row  = blockIdx.x * 8 + (threadIdx.x >> 5);
    int lane = threadIdx.x & 31;
    const float* src = w + (size_t)row * DIM;
    float vals[8];
    float sum = 0.f;
#pragma unroll
    for (int j = 0; j < 8; j++) {
        float x = src[lane + 32 * j];
        vals[j] = x;
        sum += x * x;
    }
#pragma unroll
    for (int o = 16; o; o >>= 1) sum += __shfl_xor_sync(0xFFFFFFFFu, sum, o);
    float m = fmaxf(__fsqrt_rn(sum), 1e-12f);
    float* en = g_en + (size_t)row * DIM;
    __nv_bfloat16* dst = g_B + (size_t)row * K3;
#pragma unroll
    for (int j = 0; j < 8; j++) {
        int c = lane + 32 * j;
        float xn = __fdiv_rn(vals[j], m);
        en[c] = xn;
        __nv_bfloat16 hi = __float2bfloat16(xn);
        __nv_bfloat16 lo = __float2bfloat16(xn - __bfloat162float(hi));
        dst[c] = hi; dst[DIM + c] = lo; dst[2 * DIM + c] = hi;
    }
}

// ================= HMMA GEMM (K=768 bf16) + fused argmax =================
// 256 threads, warps 4(m) x 2(n): warp tile 32x64. 3-stage cp.async pipeline.
__global__ __launch_bounds__(256, 2) void k_gemm() {
    extern __shared__ char sm[];
    __shared__ unsigned long long sBest[BM];
    uint32_t sb = smem_u32(sm);
    int tid = threadIdx.x;
    int wid = tid >> 5, lane = tid & 31;
    int warpM = wid & 3;       // 0..3 -> m offset 32*warpM
    int warpN = wid >> 2;      // 0..1 -> n offset 64*warpN

    int rowBase = blockIdx.y * BM;
    int colBase = blockIdx.x * BN;
    const __nv_bfloat16* Ag = g_A + (size_t)rowBase * K3;
    const __nv_bfloat16* Bg = g_B + (size_t)colBase * K3;

    if (tid < BM) sBest[tid] = 0ULL;

    float acc[2][8][4];
#pragma unroll
    for (int i = 0; i < 2; i++)
#pragma unroll
        for (int j = 0; j < 8; j++)
#pragma unroll
            for (int q = 0; q < 4; q++) acc[i][j][q] = 0.f;

    // per-thread load chunks (512 chunks of 16B per operand per stage)
    int c0 = tid, c1 = tid + 256;
    int ar0 = c0 >> 2, ak0 = (c0 & 3);
    int ar1 = c1 >> 2, ak1 = (c1 & 3);

#define LOAD_STAGE(s) do {                                                        \
    int k0 = (s) * BK;                                                            \
    uint32_t base = sb + ((s) % NSTAGE) * STAGE_BYTES;                            \
    cp16(base + ar0 * ROWB + ak0 * 16, Ag + (size_t)ar0 * K3 + k0 + ak0 * 8);     \
    cp16(base + ar1 * ROWB + ak1 * 16, Ag + (size_t)ar1 * K3 + k0 + ak1 * 8);     \
    cp16(base + STAGE_A + ar0 * ROWB + ak0 * 16, Bg + (size_t)ar0 * K3 + k0 + ak0 * 8); \
    cp16(base + STAGE_A + ar1 * ROWB + ak1 * 16, Bg + (size_t)ar1 * K3 + k0 + ak1 * 8); \
} while (0)

    LOAD_STAGE(0); CP_COMMIT();
    LOAD_STAGE(1); CP_COMMIT();

    // precomputed ldmatrix address offsets (within a stage buffer)
    int aRow = warpM * 32 + (lane & 15);
    int aColB = ((lane >> 4) << 3) * 2;                       // 0 or 16 bytes
    int bRow = warpN * 64 + (lane & 7) + ((lane >> 4) << 3);  // n row
    int bColB = (((lane >> 3) & 1) << 3) * 2;                 // 0 or 16 bytes

    for (int s = 0; s < KSTEPS; s++) {
        __syncthreads();                       // protect buffer (s+2)%3 from stage s-1 readers
        if (s + 2 < KSTEPS) LOAD_STAGE(s + 2);
        CP_COMMIT();
        CP_WAIT2();
        __syncthreads();

        uint32_t aBase = sb + (s % NSTAGE) * STAGE_BYTES;
        uint32_t bBase = aBase + STAGE_A;
#pragma unroll
        for (int ks = 0; ks < 2; ks++) {
            uint32_t a[2][4];
#pragma unroll
            for (int mi = 0; mi < 2; mi++)
                ldsm4(a[mi], aBase + (aRow + mi * 16) * ROWB + ks * 32 + aColB);
            uint32_t b[4][4];
#pragma unroll
            for (int nb = 0; nb < 4; nb++)
                ldsm4(b[nb], bBase + (bRow + nb * 16) * ROWB + ks * 32 + bColB);
#pragma unroll
            for (int mi = 0; mi < 2; mi++)
#pragma unroll
                for (int ni = 0; ni < 8; ni++) {
                    const uint32_t* bp = &b[ni >> 1][(ni & 1) * 2];
                    mma16816(acc[mi][ni], a[mi], bp[0], bp[1]);
                }
        }
    }

    // ---- argmax epilogue from accumulator registers ----
    // d-frag: regs {0,1}: row = base + lane>>2, cols (lane&3)*2 + {0,1}
    //         regs {2,3}: row + 8, same cols
#pragma unroll
    for (int mi = 0; mi < 2; mi++) {
#pragma unroll
        for (int half = 0; half < 2; half++) {
            float best = -1e30f;
            int bc = 0;
#pragma unroll
            for (int ni = 0; ni < 8; ni++) {
                float v0 = acc[mi][ni][half * 2];
                float v1 = acc[mi][ni][half * 2 + 1];
                int cb = warpN * 64 + ni * 8 + (lane & 3) * 2;
                if (v0 > best) { best = v0; bc = cb; }
                if (v1 > best) { best = v1; bc = cb + 1; }
            }
            int r = warpM * 32 + mi * 16 + half * 8 + (lane >> 2);
            unsigned col = (unsigned)(colBase + bc);
            unsigned long long key =
                ((unsigned long long)enc_f(best) << 32) | (unsigned long long)(0xFFFFFFFFu - col);
            atomicMax(&sBest[r], key);
        }
    }
    __syncthreads();
    if (tid < BM) atomicMax(&g_best[rowBase + tid], sBest[tid]);
#undef LOAD_STAGE
}

// ============================ output ============================
__global__ void k_out(float* __restrict__ out) {
    __shared__ unsigned kidx[32];
    int bh = blockIdx.x;
    int b = bh >> 5, h = bh & 31;
    int tx = threadIdx.x & 31;
    int ty = threadIdx.x >> 5;
    int n = bh * 32 + tx;
    if (ty == 0) {
        unsigned long long key = g_best[n];
        unsigned k = 0xFFFFFFFFu - (unsigned)(key & 0xFFFFFFFFu);
        kidx[tx] = k;
        out[(size_t)NVEC * DIM + n] = (float)k;
    }
    __syncthreads();
    unsigned k = kidx[tx];
    const float* src = g_en + (size_t)k * DIM;
    float* zq = out + (size_t)b * Cc * Hc * Wc + (size_t)h * Wc;
#pragma unroll
    for (int j = 0; j < 32; j++) {
        int c = ty + 8 * j;
        zq[(size_t)c * Hc * Wc + tx] = src[c];
    }
}

extern "C" void kernel_launch(void* const* d_in, const int* in_sizes, int n_in,
                              void* d_out, int out_size) {
    (void)n_in; (void)out_size;
    const float* z = (const float*)d_in[0];
    const float* w = (const float*)d_in[1];
    if (in_sizes[0] == NUM_E * DIM) { const float* t = z; z = w; w = t; }

    cudaFuncSetAttribute(k_gemm, cudaFuncAttributeMaxDynamicSharedMemorySize, SMEM_TOTAL);

    k_init<<<NVEC / 256, 256>>>();
    k_prep_a<<<Bc * Hc, 256>>>(z);
    k_prep_b<<<NUM_E / 8, 256>>>(w);
    dim3 grid(NUM_E / BN, NVEC / BM);
    k_gemm<<<grid, 256, SMEM_TOTAL>>>();
    k_out<<<Bc * Hc, 256>>>((float*)d_out);
}

// round 5
// speedup vs baseline: 3.0817x; 1.2413x over previous
#include <cuda_runtime.h>
#include <cuda_fp16.h>
#include <cstdint>

#define NUM_E  16384
#define DIM    256
#define NVEC   8192
#define Bc     8
#define Cc     256
#define Hc     32
#define Wc     32

#define BM 128
#define BN 128
#define BK 32
#define KSTEPS (DIM / BK)          // 8
#define ROWB   80                  // 64B data + 16B pad (conflict-free ldmatrix)
#define STAGE_A (BM * ROWB)
#define STAGE_BYTES (STAGE_A + BN * ROWB)   // 20480
#define NSTAGE 4
#define SMEM_TOTAL (NSTAGE * STAGE_BYTES)   // 81920

#define MARGIN 0.02f

// ---- scratch (__device__ globals; allocations forbidden) ----
__device__ __align__(256) __half g_Ah[(size_t)NVEC * DIM];     // 4 MB   fp16(z^T)
__device__ __align__(256) __half g_Bh[(size_t)NUM_E * DIM];    // 8 MB   fp16(normalized emb)
__device__ __align__(256) float  g_zf[(size_t)NVEC * DIM];     // 8 MB   fp32 z^T (rescore)
__device__ __align__(256) float  g_en[(size_t)NUM_E * DIM];    // 16 MB  fp32 normalized emb
__device__ __align__(256) __half g_s16[(size_t)NVEC * NUM_E];  // 256 MB screen scores
__device__ float    g_norm[NVEC];                              // ||z_row||
__device__ unsigned g_max16[NVEC];                             // enc(max fp16 score)
__device__ unsigned long long g_best[NVEC];                    // packed (enc(fp32)<<32)|~col

// ======================= helpers =======================
__device__ __forceinline__ uint32_t smem_u32(const void* p) {
    uint32_t a;
    asm("{ .reg .u64 t; cvta.to.shared.u64 t, %1; cvt.u32.u64 %0, t; }" : "=r"(a) : "l"(p));
    return a;
}
__device__ __forceinline__ void cp16(uint32_t dst, const void* src) {
    asm volatile("cp.async.cg.shared.global [%0], [%1], 16;" :: "r"(dst), "l"(src));
}
#define CP_COMMIT() asm volatile("cp.async.commit_group;" ::: "memory")
#define CP_WAIT2()  asm volatile("cp.async.wait_group 2;" ::: "memory")

__device__ __forceinline__ void ldsm4(uint32_t* r, uint32_t addr) {
    asm volatile("ldmatrix.sync.aligned.m8n8.x4.shared.b16 {%0,%1,%2,%3}, [%4];"
        : "=r"(r[0]), "=r"(r[1]), "=r"(r[2]), "=r"(r[3]) : "r"(addr));
}
__device__ __forceinline__ void mma16816(float* d, const uint32_t* a, uint32_t b0, uint32_t b1) {
    asm volatile("mma.sync.aligned.m16n8k16.row.col.f32.f16.f16.f32 "
        "{%0,%1,%2,%3}, {%4,%5,%6,%7}, {%8,%9}, {%0,%1,%2,%3};"
        : "+f"(d[0]), "+f"(d[1]), "+f"(d[2]), "+f"(d[3])
        : "r"(a[0]), "r"(a[1]), "r"(a[2]), "r"(a[3]), "r"(b0), "r"(b1));
}
__device__ __forceinline__ unsigned enc_f(float f) {
    unsigned u = __float_as_uint(f);
    return (u & 0x80000000u) ? ~u : (u | 0x80000000u);
}
__device__ __forceinline__ float dec_f(unsigned e) {
    unsigned u = (e & 0x80000000u) ? (e & 0x7FFFFFFFu) : ~e;
    return __uint_as_float(u);
}

// ============================== init ==============================
__global__ void k_init() {
    int i = blockIdx.x * 256 + threadIdx.x;
    g_best[i] = 0ULL;
    g_max16[i] = 0u;
}

// ============ prep A: transpose z, fp32 + fp16 copies, row norms ============
__global__ void k_prep_a(const float* __restrict__ z) {
    __shared__ float s[DIM][33];
    int bh = blockIdx.x;
    int b = bh >> 5, h = bh & 31;
    int tx = threadIdx.x & 31;   // w
    int ty = threadIdx.x >> 5;   // 0..7
    const float* base = z + (size_t)b * Cc * Hc * Wc + (size_t)h * Wc;
#pragma unroll
    for (int j = 0; j < 32; j++) {
        int c = ty + 8 * j;
        s[c][tx] = base[(size_t)c * Hc * Wc + tx];
    }
    __syncthreads();
#pragma unroll
    for (int m = 0; m < 4; m++) {
        int wv = ty + 8 * m;
        int n = bh * 32 + wv;
        float* zf = g_zf + (size_t)n * DIM;
        __half* ah = g_Ah + (size_t)n * DIM;
        float ss = 0.f;
#pragma unroll
        for (int j = 0; j < 8; j++) {
            int c = tx + 32 * j;
            float x = s[c][wv];
            zf[c] = x;
            ah[c] = __float2half(x);
            ss += x * x;
        }
#pragma unroll
        for (int o = 16; o; o >>= 1) ss += __shfl_xor_sync(0xFFFFFFFFu, ss, o);
        if (tx == 0) g_norm[n] = __fsqrt_rn(ss);
    }
}

// ============ prep B: normalize codebook, fp32 + fp16 copies ============
__global__ void k_prep_b(const float* __restrict__ w) {
    int row  = blockIdx.x * 8 + (threadIdx.x >> 5);
    int lane = threadIdx.x & 31;
    const float* src = w + (size_t)row * DIM;
    float vals[8];
    float sum = 0.f;
#pragma unroll
    for (int j = 0; j < 8; j++) {
        float x = src[lane + 32 * j];
        vals[j] = x;
        sum += x * x;
    }
#pragma unroll
    for (int o = 16; o; o >>= 1) sum += __shfl_xor_sync(0xFFFFFFFFu, sum, o);
    float m = fmaxf(__fsqrt_rn(sum), 1e-12f);
    float* en = g_en + (size_t)row * DIM;
    __half* bh = g_Bh + (size_t)row * DIM;
#pragma unroll
    for (int j = 0; j < 8; j++) {
        int c = lane + 32 * j;
        float xn = __fdiv_rn(vals[j], m);
        en[c] = xn;
        bh[c] = __float2half(xn);
    }
}

// ========== fp16 screen GEMM (K=256): scores + per-row fp16 max ==========
__global__ __launch_bounds__(256, 2) void k_gemm() {
    extern __shared__ char sm[];
    __shared__ unsigned sMax[BM];
    uint32_t sb = smem_u32(sm);
    int tid = threadIdx.x;
    int wid = tid >> 5, lane = tid & 31;
    int warpM = wid & 3;
    int warpN = wid >> 2;

    int rowBase = blockIdx.y * BM;
    int colBase = blockIdx.x * BN;
    const __half* Ag = g_Ah + (size_t)rowBase * DIM;
    const __half* Bg = g_Bh + (size_t)colBase * DIM;

    if (tid < BM) sMax[tid] = 0u;

    float acc[2][8][4];
#pragma unroll
    for (int i = 0; i < 2; i++)
#pragma unroll
        for (int j = 0; j < 8; j++)
#pragma unroll
            for (int q = 0; q < 4; q++) acc[i][j][q] = 0.f;

    int c0 = tid, c1 = tid + 256;          // 512 16B-chunks per operand per stage
    int ar0 = c0 >> 2, ak0 = c0 & 3;
    int ar1 = c1 >> 2, ak1 = c1 & 3;

#define LOAD_STAGE(s) do {                                                        \
    int k0 = (s) * BK;                                                            \
    uint32_t base = sb + ((s) % NSTAGE) * STAGE_BYTES;                            \
    cp16(base + ar0 * ROWB + ak0 * 16, Ag + (size_t)ar0 * DIM + k0 + ak0 * 8);    \
    cp16(base + ar1 * ROWB + ak1 * 16, Ag + (size_t)ar1 * DIM + k0 + ak1 * 8);    \
    cp16(base + STAGE_A + ar0 * ROWB + ak0 * 16, Bg + (size_t)ar0 * DIM + k0 + ak0 * 8); \
    cp16(base + STAGE_A + ar1 * ROWB + ak1 * 16, Bg + (size_t)ar1 * DIM + k0 + ak1 * 8); \
} while (0)

    LOAD_STAGE(0); CP_COMMIT();
    LOAD_STAGE(1); CP_COMMIT();
    LOAD_STAGE(2); CP_COMMIT();

    int aRow  = warpM * 32 + (lane & 15);
    int aColB = (lane >> 4) * 16;
    int bRow  = warpN * 64 + (lane & 7) + ((lane >> 4) << 3);
    int bColB = ((lane >> 3) & 1) * 16;

    for (int s = 0; s < KSTEPS; s++) {
        CP_WAIT2();
        __syncthreads();                        // frees buffer (s-1)%4 for the next load
        if (s + 3 < KSTEPS) LOAD_STAGE(s + 3);
        CP_COMMIT();

        uint32_t aBase = sb + (s % NSTAGE) * STAGE_BYTES;
        uint32_t bBase = aBase + STAGE_A;
#pragma unroll
        for (int ks = 0; ks < 2; ks++) {
            uint32_t a[2][4];
#pragma unroll
            for (int mi = 0; mi < 2; mi++)
                ldsm4(a[mi], aBase + (aRow + mi * 16) * ROWB + ks * 32 + aColB);
            uint32_t b[4][4];
#pragma unroll
            for (int nb = 0; nb < 4; nb++)
                ldsm4(b[nb], bBase + (bRow + nb * 16) * ROWB + ks * 32 + bColB);
#pragma unroll
            for (int mi = 0; mi < 2; mi++)
#pragma unroll
                for (int ni = 0; ni < 8; ni++) {
                    const uint32_t* bp = &b[ni >> 1][(ni & 1) * 2];
                    mma16816(acc[mi][ni], a[mi], bp[0], bp[1]);
                }
        }
    }
#undef LOAD_STAGE

    // ---- epilogue: store fp16 scores + track per-row fp16 max ----
#pragma unroll
    for (int mi = 0; mi < 2; mi++) {
#pragma unroll
        for (int hf = 0; hf < 2; hf++) {
            int r = warpM * 32 + mi * 16 + hf * 8 + (lane >> 2);
            size_t rowOff = (size_t)(rowBase + r) * NUM_E + colBase;
            float best = -1e30f;
#pragma unroll
            for (int ni = 0; ni < 8; ni++) {
                float v0 = acc[mi][ni][hf * 2];
                float v1 = acc[mi][ni][hf * 2 + 1];
                __half2 h2 = __floats2half2_rn(v0, v1);
                int cb = warpN * 64 + ni * 8 + (lane & 3) * 2;
                *(__half2*)(g_s16 + rowOff + cb) = h2;
                float hv0 = __low2float(h2), hv1 = __high2float(h2);
                best = fmaxf(best, fmaxf(hv0, hv1));
            }
            atomicMax(&sMax[r], enc_f(best));
        }
    }
    __syncthreads();
    if (tid < BM) atomicMax(&g_max16[rowBase + tid], sMax[tid]);
}

// ========== scan: candidates within margin of row max -> fp32 rescore ==========
__global__ __launch_bounds__(256) void k_scan() {
    int n = blockIdx.x;
    __shared__ __align__(16) float zrow[DIM];   // 16B-aligned: read as float4 below
    __shared__ float thr;
    zrow[threadIdx.x] = g_zf[(size_t)n * DIM + threadIdx.x];
    if (threadIdx.x == 0)
        thr = dec_f(g_max16[n]) - MARGIN * g_norm[n];
    __syncthreads();
    float t = thr;
    const uint4* srow = (const uint4*)(g_s16 + (size_t)n * NUM_E);
#pragma unroll
    for (int j = 0; j < 8; j++) {
        int idx = j * 256 + threadIdx.x;        // uint4 = 8 halves
        uint4 v = srow[idx];
        __half2 hs[4] = {*(__half2*)&v.x, *(__half2*)&v.y, *(__half2*)&v.z, *(__half2*)&v.w};
#pragma unroll
        for (int q = 0; q < 4; q++) {
            float2 f = __half22float2(hs[q]);
#pragma unroll
            for (int p = 0; p < 2; p++) {
                float sv = p ? f.y : f.x;
                if (sv >= t) {
                    int col = idx * 8 + q * 2 + p;
                    const float4* ep = (const float4*)(g_en + (size_t)col * DIM);
                    const float4* zp = (const float4*)zrow;
                    float s = 0.f;
#pragma unroll 8
                    for (int d = 0; d < DIM / 4; d++) {
                        float4 e = ep[d], zz = zp[d];
                        s += zz.x * e.x + zz.y * e.y + zz.z * e.z + zz.w * e.w;
                    }
                    unsigned long long key = ((unsigned long long)enc_f(s) << 32)
                                           | (unsigned long long)(0xFFFFFFFFu - (unsigned)col);
                    atomicMax(&g_best[n], key);
                }
            }
        }
    }
}

// ============================ output ============================
__global__ void k_out(float* __restrict__ out) {
    __shared__ unsigned kidx[32];
    int bh = blockIdx.x;
    int b = bh >> 5, h = bh & 31;
    int tx = threadIdx.x & 31;
    int ty = threadIdx.x >> 5;
    int n = bh * 32 + tx;
    if (ty == 0) {
        unsigned long long key = g_best[n];
        unsigned k = 0xFFFFFFFFu - (unsigned)(key & 0xFFFFFFFFu);
        kidx[tx] = k;
        out[(size_t)NVEC * DIM + n] = (float)k;
    }
    __syncthreads();
    unsigned k = kidx[tx];
    const float* src = g_en + (size_t)k * DIM;
    float* zq = out + (size_t)b * Cc * Hc * Wc + (size_t)h * Wc;
#pragma unroll
    for (int j = 0; j < 32; j++) {
        int c = ty + 8 * j;
        zq[(size_t)c * Hc * Wc + tx] = src[c];
    }
}

extern "C" void kernel_launch(void* const* d_in, const int* in_sizes, int n_in,
                              void* d_out, int out_size) {
    (void)n_in; (void)out_size;
    const float* z = (const float*)d_in[0];
    const float* w = (const float*)d_in[1];
    if (in_sizes[0] == NUM_E * DIM) { const float* t = z; z = w; w = t; }

    cudaFuncSetAttribute(k_gemm, cudaFuncAttributeMaxDynamicSharedMemorySize, SMEM_TOTAL);

    k_init<<<NVEC / 256, 256>>>();
    k_prep_a<<<Bc * Hc, 256>>>(z);
    k_prep_b<<<NUM_E / 8, 256>>>(w);
    dim3 grid(NUM_E / BN, NVEC / BM);
    k_gemm<<<grid, 256, SMEM_TOTAL>>>();
    k_scan<<<NVEC, 256>>>();
    k_out<<<Bc * Hc, 256>>>((float*)d_out);
}

// round 6
// speedup vs baseline: 4.1562x; 1.3487x over previous
#include <cuda_runtime.h>
#include <cuda_fp16.h>
#include <cstdint>

#define NUM_E  16384
#define DIM    256
#define NVEC   8192
#define Bc     8
#define Cc     256
#define Hc     32
#define Wc     32

#define BM 128
#define BN 128
#define BK 32
#define KSTEPS (DIM / BK)          // 8
#define ROWB   80                  // 64B data + 16B pad (conflict-free ldmatrix)
#define STAGE_A (BM * ROWB)
#define STAGE_BYTES (STAGE_A + BN * ROWB)   // 20480
#define NSTAGE 4
#define SMEM_TOTAL (NSTAGE * STAGE_BYTES)   // 81920

#define CAP 1024                   // candidate list capacity (overflow -> slow path)

// ---- scratch (__device__ globals; allocations forbidden) ----
__device__ __align__(256) __half g_Ah[(size_t)NVEC * DIM];     // 4 MB   fp16(z^T)
__device__ __align__(256) __half g_Bh[(size_t)NUM_E * DIM];    // 8 MB   fp16(normalized emb)
__device__ __align__(256) float  g_zf[(size_t)NVEC * DIM];     // 8 MB   fp32 z^T (rescore)
__device__ __align__(256) float  g_en[(size_t)NUM_E * DIM];    // 16 MB  fp32 normalized emb
__device__ float    g_norm[NVEC];                              // ||z_row||
__device__ unsigned g_max16[NVEC];                             // enc(running global mma max)
__device__ unsigned long long g_best[NVEC];                    // packed (enc(fp32)<<32)|~col

// ======================= helpers =======================
__device__ __forceinline__ uint32_t smem_u32(const void* p) {
    uint32_t a;
    asm("{ .reg .u64 t; cvta.to.shared.u64 t, %1; cvt.u32.u64 %0, t; }" : "=r"(a) : "l"(p));
    return a;
}
__device__ __forceinline__ void cp16(uint32_t dst, const void* src) {
    asm volatile("cp.async.cg.shared.global [%0], [%1], 16;" :: "r"(dst), "l"(src));
}
#define CP_COMMIT() asm volatile("cp.async.commit_group;" ::: "memory")
#define CP_WAIT2()  asm volatile("cp.async.wait_group 2;" ::: "memory")

__device__ __forceinline__ void ldsm4(uint32_t* r, uint32_t addr) {
    asm volatile("ldmatrix.sync.aligned.m8n8.x4.shared.b16 {%0,%1,%2,%3}, [%4];"
        : "=r"(r[0]), "=r"(r[1]), "=r"(r[2]), "=r"(r[3]) : "r"(addr));
}
__device__ __forceinline__ void mma16816(float* d, const uint32_t* a, uint32_t b0, uint32_t b1) {
    asm volatile("mma.sync.aligned.m16n8k16.row.col.f32.f16.f16.f32 "
        "{%0,%1,%2,%3}, {%4,%5,%6,%7}, {%8,%9}, {%0,%1,%2,%3};"
        : "+f"(d[0]), "+f"(d[1]), "+f"(d[2]), "+f"(d[3])
        : "r"(a[0]), "r"(a[1]), "r"(a[2]), "r"(a[3]), "r"(b0), "r"(b1));
}
__device__ __forceinline__ unsigned enc_f(float f) {
    unsigned u = __float_as_uint(f);
    return (u & 0x80000000u) ? ~u : (u | 0x80000000u);
}
__device__ __forceinline__ float dec_f(unsigned e) {
    unsigned u = (e & 0x80000000u) ? (e & 0x7FFFFFFFu) : ~e;
    return __uint_as_float(u);
}

// ============================== init ==============================
__global__ void k_init() {
    int i = blockIdx.x * 256 + threadIdx.x;
    g_best[i] = 0ULL;
    g_max16[i] = 0u;   // any real enc() is > 0, so this acts as -inf
}

// ============ prep A: transpose z, fp32 + fp16 copies, row norms ============
__global__ void k_prep_a(const float* __restrict__ z) {
    __shared__ float s[DIM][33];
    int bh = blockIdx.x;
    int b = bh >> 5, h = bh & 31;
    int tx = threadIdx.x & 31;   // w
    int ty = threadIdx.x >> 5;   // 0..7
    const float* base = z + (size_t)b * Cc * Hc * Wc + (size_t)h * Wc;
#pragma unroll
    for (int j = 0; j < 32; j++) {
        int c = ty + 8 * j;
        s[c][tx] = base[(size_t)c * Hc * Wc + tx];
    }
    __syncthreads();
#pragma unroll
    for (int m = 0; m < 4; m++) {
        int wv = ty + 8 * m;
        int n = bh * 32 + wv;
        float* zf = g_zf + (size_t)n * DIM;
        __half* ah = g_Ah + (size_t)n * DIM;
        float ss = 0.f;
#pragma unroll
        for (int j = 0; j < 8; j++) {
            int c = tx + 32 * j;
            float x = s[c][wv];
            zf[c] = x;
            ah[c] = __float2half(x);
            ss += x * x;
        }
#pragma unroll
        for (int o = 16; o; o >>= 1) ss += __shfl_xor_sync(0xFFFFFFFFu, ss, o);
        if (tx == 0) g_norm[n] = __fsqrt_rn(ss);
    }
}

// ============ prep B: normalize codebook, fp32 + fp16 copies ============
__global__ void k_prep_b(const float* __restrict__ w) {
    int row  = blockIdx.x * 8 + (threadIdx.x >> 5);
    int lane = threadIdx.x & 31;
    const float* src = w + (size_t)row * DIM;
    float vals[8];
    float sum = 0.f;
#pragma unroll
    for (int j = 0; j < 8; j++) {
        float x = src[lane + 32 * j];
        vals[j] = x;
        sum += x * x;
    }
#pragma unroll
    for (int o = 16; o; o >>= 1) sum += __shfl_xor_sync(0xFFFFFFFFu, sum, o);
    float m = fmaxf(__fsqrt_rn(sum), 1e-12f);
    float* en = g_en + (size_t)row * DIM;
    __half* bh = g_Bh + (size_t)row * DIM;
#pragma unroll
    for (int j = 0; j < 8; j++) {
        int c = lane + 32 * j;
        float xn = __fdiv_rn(vals[j], m);
        en[c] = xn;
        bh[c] = __float2half(xn);
    }
}

// ===== fused fp16 screen GEMM + running-max filter + fp32 rescore =====
__global__ __launch_bounds__(256, 2) void k_gemm() {
    extern __shared__ char sm[];
    __shared__ unsigned sMax[BM];
    __shared__ float    sThr[BM];
    __shared__ unsigned sList[CAP];
    __shared__ int      sCnt;
    uint32_t sb = smem_u32(sm);
    int tid = threadIdx.x;
    int wid = tid >> 5, lane = tid & 31;
    int warpM = wid & 3;
    int warpN = wid >> 2;

    int rowBase = blockIdx.y * BM;
    int colBase = blockIdx.x * BN;
    const __half* Ag = g_Ah + (size_t)rowBase * DIM;
    const __half* Bg = g_Bh + (size_t)colBase * DIM;

    if (tid < BM) sMax[tid] = 0u;
    if (tid == 0) sCnt = 0;

    float acc[2][8][4];
#pragma unroll
    for (int i = 0; i < 2; i++)
#pragma unroll
        for (int j = 0; j < 8; j++)
#pragma unroll
            for (int q = 0; q < 4; q++) acc[i][j][q] = 0.f;

    int c0 = tid, c1 = tid + 256;
    int ar0 = c0 >> 2, ak0 = c0 & 3;
    int ar1 = c1 >> 2, ak1 = c1 & 3;

#define LOAD_STAGE(s) do {                                                        \
    int k0 = (s) * BK;                                                            \
    uint32_t base = sb + ((s) % NSTAGE) * STAGE_BYTES;                            \
    cp16(base + ar0 * ROWB + ak0 * 16, Ag + (size_t)ar0 * DIM + k0 + ak0 * 8);    \
    cp16(base + ar1 * ROWB + ak1 * 16, Ag + (size_t)ar1 * DIM + k0 + ak1 * 8);    \
    cp16(base + STAGE_A + ar0 * ROWB + ak0 * 16, Bg + (size_t)ar0 * DIM + k0 + ak0 * 8); \
    cp16(base + STAGE_A + ar1 * ROWB + ak1 * 16, Bg + (size_t)ar1 * DIM + k0 + ak1 * 8); \
} while (0)

    LOAD_STAGE(0); CP_COMMIT();
    LOAD_STAGE(1); CP_COMMIT();
    LOAD_STAGE(2); CP_COMMIT();

    int aRow  = warpM * 32 + (lane & 15);
    int aColB = (lane >> 4) * 16;
    int bRow  = warpN * 64 + (lane & 7) + ((lane >> 4) << 3);
    int bColB = ((lane >> 3) & 1) * 16;

    for (int s = 0; s < KSTEPS; s++) {
        CP_WAIT2();
        __syncthreads();
        if (s + 3 < KSTEPS) LOAD_STAGE(s + 3);
        CP_COMMIT();

        uint32_t aBase = sb + (s % NSTAGE) * STAGE_BYTES;
        uint32_t bBase = aBase + STAGE_A;
#pragma unroll
        for (int ks = 0; ks < 2; ks++) {
            uint32_t a[2][4];
#pragma unroll
            for (int mi = 0; mi < 2; mi++)
                ldsm4(a[mi], aBase + (aRow + mi * 16) * ROWB + ks * 32 + aColB);
            uint32_t b[4][4];
#pragma unroll
            for (int nb = 0; nb < 4; nb++)
                ldsm4(b[nb], bBase + (bRow + nb * 16) * ROWB + ks * 32 + bColB);
#pragma unroll
            for (int mi = 0; mi < 2; mi++)
#pragma unroll
                for (int ni = 0; ni < 8; ni++) {
                    const uint32_t* bp = &b[ni >> 1][(ni & 1) * 2];
                    mma16816(acc[mi][ni], a[mi], bp[0], bp[1]);
                }
        }
    }
#undef LOAD_STAGE

    // ---- 1. per-row tile maxes into shared ----
#pragma unroll
    for (int mi = 0; mi < 2; mi++) {
#pragma unroll
        for (int hf = 0; hf < 2; hf++) {
            float mx = -1e30f;
#pragma unroll
            for (int ni = 0; ni < 8; ni++)
                mx = fmaxf(mx, fmaxf(acc[mi][ni][hf * 2], acc[mi][ni][hf * 2 + 1]));
            int r = warpM * 32 + mi * 16 + hf * 8 + (lane >> 2);
            atomicMax(&sMax[r], enc_f(mx));
        }
    }
    __syncthreads();

    // ---- 2. merge with running global max; derive threshold ----
    if (tid < BM) {
        int R = rowBase + tid;
        unsigned mine = sMax[tid];
        unsigned old  = atomicMax(&g_max16[R], mine);
        unsigned cur  = old > mine ? old : mine;
        // margin 0.004*||z|| > 2 * fp16-mma error bound (2^-10*||z||)
        sThr[tid] = dec_f(cur) - 0.004f * g_norm[R];
    }
    __syncthreads();

    // ---- 3. collect candidates (superset of within-margin-of-global-max) ----
#pragma unroll
    for (int mi = 0; mi < 2; mi++) {
#pragma unroll
        for (int hf = 0; hf < 2; hf++) {
            int r = warpM * 32 + mi * 16 + hf * 8 + (lane >> 2);
            float t = sThr[r];
#pragma unroll
            for (int ni = 0; ni < 8; ni++) {
#pragma unroll
                for (int p = 0; p < 2; p++) {
                    float v = acc[mi][ni][hf * 2 + p];
                    if (v >= t) {
                        int c = warpN * 64 + ni * 8 + (lane & 3) * 2 + p;
                        int idx = atomicAdd(&sCnt, 1);
                        if (idx < CAP) {
                            sList[idx] = ((unsigned)r << 16) | (unsigned)c;
                        } else {
                            // overflow slow path (statistically never): scalar fp32 dot
                            int R = rowBase + r, C = colBase + c;
                            const float* zp = g_zf + (size_t)R * DIM;
                            const float* ep = g_en + (size_t)C * DIM;
                            float sdot = 0.f;
                            for (int d = 0; d < DIM; d++) sdot += zp[d] * ep[d];
                            unsigned long long key = ((unsigned long long)enc_f(sdot) << 32)
                                | (unsigned long long)(0xFFFFFFFFu - (unsigned)C);
                            atomicMax(&g_best[R], key);
                        }
                    }
                }
            }
        }
    }
    __syncthreads();

    // ---- 4. warp-cooperative fp32 rescore of candidates ----
    int cnt = sCnt < CAP ? sCnt : CAP;
    for (int i = wid; i < cnt; i += 8) {
        unsigned e = sList[i];
        int R = rowBase + (int)(e >> 16);
        int C = colBase + (int)(e & 0xFFFFu);
        const float4* zp = (const float4*)(g_zf + (size_t)R * DIM);
        const float4* ep = (const float4*)(g_en + (size_t)C * DIM);
        float4 a0 = zp[lane * 2],     b0 = ep[lane * 2];
        float4 a1 = zp[lane * 2 + 1], b1 = ep[lane * 2 + 1];
        float sdot = a0.x * b0.x + a0.y * b0.y + a0.z * b0.z + a0.w * b0.w
                   + a1.x * b1.x + a1.y * b1.y + a1.z * b1.z + a1.w * b1.w;
#pragma unroll
        for (int o = 16; o; o >>= 1) sdot += __shfl_xor_sync(0xFFFFFFFFu, sdot, o);
        if (lane == 0) {
            unsigned long long key = ((unsigned long long)enc_f(sdot) << 32)
                | (unsigned long long)(0xFFFFFFFFu - (unsigned)C);
            atomicMax(&g_best[R], key);
        }
    }
}

// ============================ output ============================
__global__ void k_out(float* __restrict__ out) {
    __shared__ unsigned kidx[32];
    int bh = blockIdx.x;
    int b = bh >> 5, h = bh & 31;
    int tx = threadIdx.x & 31;
    int ty = threadIdx.x >> 5;
    int n = bh * 32 + tx;
    if (ty == 0) {
        unsigned long long key = g_best[n];
        unsigned k = 0xFFFFFFFFu - (unsigned)(key & 0xFFFFFFFFu);
        kidx[tx] = k;
        out[(size_t)NVEC * DIM + n] = (float)k;
    }
    __syncthreads();
    unsigned k = kidx[tx];
    const float* src = g_en + (size_t)k * DIM;
    float* zq = out + (size_t)b * Cc * Hc * Wc + (size_t)h * Wc;
#pragma unroll
    for (int j = 0; j < 32; j++) {
        int c = ty + 8 * j;
        zq[(size_t)c * Hc * Wc + tx] = src[c];
    }
}

extern "C" void kernel_launch(void* const* d_in, const int* in_sizes, int n_in,
                              void* d_out, int out_size) {
    (void)n_in; (void)out_size;
    const float* z = (const float*)d_in[0];
    const float* w = (const float*)d_in[1];
    if (in_sizes[0] == NUM_E * DIM) { const float* t = z; z = w; w = t; }

    cudaFuncSetAttribute(k_gemm, cudaFuncAttributeMaxDynamicSharedMemorySize, SMEM_TOTAL);

    k_init<<<NVEC / 256, 256>>>();
    k_prep_a<<<Bc * Hc, 256>>>(z);
    k_prep_b<<<NUM_E / 8, 256>>>(w);
    dim3 grid(NUM_E / BN, NVEC / BM);
    k_gemm<<<grid, 256, SMEM_TOTAL>>>();
    k_out<<<Bc * Hc, 256>>>((float*)d_out);
}